// round 10
// baseline (speedup 1.0000x reference)
#include <cuda_runtime.h>

// ---------------------------------------------------------------------------
// MLS-MPM single step, 500k particles, 64^3 grid — sorted pipeline v9.
//   hist(rank-pack) -> scan1 -> scan23(+zero count, sentinel)
//   -> scatter (smem-staged coalesced reads, single 64B record write)
//   -> per-cell P2G (3 threads/cell, one a-plane each, red.v4, prefetch)
//   -> grid -> sorted G2P -> final(unsort + F, zero grid).
// ---------------------------------------------------------------------------

namespace {
constexpr int   NG      = 64;
constexpr int   GSZ     = NG * NG * NG;        // 262144
constexpr int   NP      = 500000;
constexpr float INV_DXf = 64.0f;
constexpr float DXf     = 1.0f / 64.0f;
constexpr float DTf     = 5e-4f;
constexpr float P_MASSf = 4.76837158203125e-4f;   // 1000 * (DX/2)^3
constexpr float AFF_COEF = -3.90625e-6f;          // -DT*P_VOL*4*INV_DX^2
constexpr float C_COEF   = 256.0f;                // 4*INV_DX^2*DX
constexpr int   SCAN_T      = 256;
constexpr int   SCAN_BLOCKS = 256;                // 256 blocks * 1024 elems
}

__device__ float4 g_grid[GSZ];                    // (mv.xyz, m) -> (v.xyz, 0)
__device__ __align__(16) int g_count[GSZ];
__device__ __align__(16) int g_start[GSZ + 4];    // exclusive offsets + sentinel
__device__ int    g_bsum[SCAN_BLOCKS];
__device__ int    g_binid[NP];                    // bin | rank<<18
__device__ int    g_slot[NP];                     // original p -> sorted slot
__device__ __align__(64) float4 g_pk[4 * NP];     // 64B payload records  32 MB
__device__ float4 g_outbuf[3 * NP];               // (v',C')              24 MB

// ---------------------------------------------------------------------------
__device__ __forceinline__ int clampi(int v, int lo, int hi) {
    return v < lo ? lo : (v > hi ? hi : v);
}

// hist: bin count + per-particle rank via atomic return; pack bin|rank<<18.
__global__ void __launch_bounds__(256) hist_kernel(const float* __restrict__ x) {
    int p = blockIdx.x * 256 + threadIdx.x;
    if (p >= NP) return;
    const float gx = x[3 * p + 0] * INV_DXf;
    const float gy = x[3 * p + 1] * INV_DXf;
    const float gz = x[3 * p + 2] * INV_DXf;
    const int bx = clampi((int)floorf(gx - 0.5f), 0, NG - 3);
    const int by = clampi((int)floorf(gy - 0.5f), 0, NG - 3);
    const int bz = clampi((int)floorf(gz - 0.5f), 0, NG - 3);
    const int bin = (bx * NG + by) * NG + bz;
    const int rank = atomicAdd(&g_count[bin], 1);
    g_binid[p] = bin | (rank << 18);
}

// ---------------------------------------------------------------------------
// scan1: per-block (1024 elems) exclusive scan into g_start, totals to g_bsum.
__global__ void __launch_bounds__(SCAN_T) scan1_kernel() {
    __shared__ int sh[SCAN_T];
    const int t = threadIdx.x, b = blockIdx.x;
    const int4 cv = reinterpret_cast<const int4*>(g_count)[b * SCAN_T + t];
    const int ts = cv.x + cv.y + cv.z + cv.w;
    sh[t] = ts;
    __syncthreads();
#pragma unroll
    for (int off = 1; off < SCAN_T; off <<= 1) {
        int a = (t >= off) ? sh[t - off] : 0;
        __syncthreads();
        sh[t] += a;
        __syncthreads();
    }
    const int excl = sh[t] - ts;
    int4 ov;
    ov.x = excl;
    ov.y = excl + cv.x;
    ov.z = excl + cv.x + cv.y;
    ov.w = excl + cv.x + cv.y + cv.z;
    reinterpret_cast<int4*>(g_start)[b * SCAN_T + t] = ov;
    if (t == SCAN_T - 1) g_bsum[b] = sh[t];
}

// scan23: block b adds sum(g_bsum[0..b)) to its 1024 elements; writes g_start;
// zeroes g_count (consumed) and writes the sentinel.
__global__ void __launch_bounds__(SCAN_T) scan23_kernel() {
    __shared__ int red[SCAN_T];
    const int t = threadIdx.x, b = blockIdx.x;
    red[t] = (t < b) ? g_bsum[t] : 0;
    __syncthreads();
#pragma unroll
    for (int off = SCAN_T / 2; off > 0; off >>= 1) {
        if (t < off) red[t] += red[t + off];
        __syncthreads();
    }
    const int offset = red[0];
    const int idx = b * SCAN_T + t;
    int4 sv = reinterpret_cast<const int4*>(g_start)[idx];
    sv.x += offset; sv.y += offset; sv.z += offset; sv.w += offset;
    reinterpret_cast<int4*>(g_start)[idx] = sv;
    reinterpret_cast<int4*>(g_count)[idx] = make_int4(0, 0, 0, 0);
    if (b == SCAN_BLOCKS - 1 && t == SCAN_T - 1) g_start[GSZ] = NP;
}

// ---------------------------------------------------------------------------
// Scatter: smem-staged coalesced input reads; one 64B record write per
// particle at sorted slot s = g_start[bin] + rank.
// Record: r0=(x,y,z,mv0) r1=(mv1,mv2,A00,A01) r2=(A02,A10,A11,A12)
//         r3=(A20,A21,A22,0)
__global__ void __launch_bounds__(256) scatter_kernel(
    const float* __restrict__ x, const float* __restrict__ v,
    const float* __restrict__ C, const float* __restrict__ S)
{
    __shared__ float sx[768];     // 256 * 3
    __shared__ float sv_[768];    // 256 * 3
    __shared__ float sC[2304];    // 256 * 9
    __shared__ float sS[2304];    // 256 * 9

    const int tid   = threadIdx.x;
    const int pbase = blockIdx.x * 256;

    if (pbase + 256 <= NP) {
        const float4* x4 = reinterpret_cast<const float4*>(x + 3 * pbase);
        const float4* v4 = reinterpret_cast<const float4*>(v + 3 * pbase);
        const float4* C4 = reinterpret_cast<const float4*>(C + 9 * pbase);
        const float4* S4 = reinterpret_cast<const float4*>(S + 9 * pbase);
        if (tid < 192) {
            reinterpret_cast<float4*>(sx)[tid]  = __ldcs(&x4[tid]);
            reinterpret_cast<float4*>(sv_)[tid] = __ldcs(&v4[tid]);
        }
#pragma unroll
        for (int i = tid; i < 576; i += 256) {
            reinterpret_cast<float4*>(sC)[i] = __ldcs(&C4[i]);
            reinterpret_cast<float4*>(sS)[i] = __ldcs(&S4[i]);
        }
    } else {
        const int nfl3 = (NP - pbase) * 3;
        const int nfl9 = (NP - pbase) * 9;
        for (int i = tid; i < nfl3; i += 256) {
            sx[i]  = x[3 * pbase + i];
            sv_[i] = v[3 * pbase + i];
        }
        for (int i = tid; i < nfl9; i += 256) {
            sC[i] = C[9 * pbase + i];
            sS[i] = S[9 * pbase + i];
        }
    }
    __syncthreads();

    const int p = pbase + tid;
    if (p >= NP) return;

    const int pk  = g_binid[p];
    const int bin = pk & 0x3FFFF;
    const int s   = __ldg(&g_start[bin]) + (pk >> 18);
    g_slot[p] = s;

    float A[9];
#pragma unroll
    for (int i = 0; i < 9; i++)
        A[i] = (sS[9 * tid + i] * AFF_COEF + P_MASSf * sC[9 * tid + i]) * DXf;
    const float mv0 = P_MASSf * sv_[3 * tid + 0];
    const float mv1 = P_MASSf * sv_[3 * tid + 1];
    const float mv2 = P_MASSf * sv_[3 * tid + 2];

    float4* r = &g_pk[4 * s];
    r[0] = make_float4(sx[3 * tid + 0], sx[3 * tid + 1], sx[3 * tid + 2], mv0);
    r[1] = make_float4(mv1, mv2, A[0], A[1]);
    r[2] = make_float4(A[2], A[3], A[4], A[5]);
    r[3] = make_float4(A[6], A[7], A[8], 0.f);
}

// ---------------------------------------------------------------------------
// Per-cell P2G, 3 threads per cell (one a-plane each): thread n -> cell n/3,
// plane a = n%3. Lanes of the same cell share payload loads (broadcast).
// Each thread accumulates 9 float4 and issues 9 red.v4.
__global__ void __launch_bounds__(256) p2g_cell_kernel() {
    const int n = blockIdx.x * 256 + threadIdx.x;
    if (n >= 3 * GSZ) return;
    const int c = n / 3;
    const int a = n - 3 * c;
    const int s0 = g_start[c];
    const int s1 = g_start[c + 1];
    if (s0 >= s1) return;

    const float bi = (float)(c >> 12);
    const float bj = (float)((c >> 6) & 63);
    const float bk = (float)(c & 63);
    const float fa = (float)a;

    float4 acc[9];
#pragma unroll
    for (int o = 0; o < 9; o++) acc[o] = make_float4(0.f, 0.f, 0.f, 0.f);

    // prime the pipeline
    float4 q0 = __ldg(&g_pk[4 * s0 + 0]);
    float4 q1 = __ldg(&g_pk[4 * s0 + 1]);
    float4 q2 = __ldg(&g_pk[4 * s0 + 2]);
    float4 q3 = __ldg(&g_pk[4 * s0 + 3]);

    for (int t = s0; t < s1; ++t) {
        float4 n0, n1, n2, n3;
        const int tn = t + 1;
        if (tn < s1) {
            n0 = __ldg(&g_pk[4 * tn + 0]);
            n1 = __ldg(&g_pk[4 * tn + 1]);
            n2 = __ldg(&g_pk[4 * tn + 2]);
            n3 = __ldg(&g_pk[4 * tn + 3]);
        }

        const float fx = q0.x * INV_DXf - bi;
        const float fy = q0.y * INV_DXf - bj;
        const float fz = q0.z * INV_DXf - bk;
        const float mv0 = q0.w, mv1 = q1.x, mv2 = q1.y;
        const float A00 = q1.z, A01 = q1.w, A02 = q2.x;
        const float A10 = q2.y, A11 = q2.z, A12 = q2.w;
        const float A20 = q3.x, A21 = q3.y, A22 = q3.z;

        float wx[3], wy[3], wz[3];
        wx[0] = 0.5f * (1.5f - fx) * (1.5f - fx);
        wx[1] = 0.75f - (fx - 1.0f) * (fx - 1.0f);
        wx[2] = 0.5f * (fx - 0.5f) * (fx - 0.5f);
        wy[0] = 0.5f * (1.5f - fy) * (1.5f - fy);
        wy[1] = 0.75f - (fy - 1.0f) * (fy - 1.0f);
        wy[2] = 0.5f * (fy - 0.5f) * (fy - 0.5f);
        wz[0] = 0.5f * (1.5f - fz) * (1.5f - fz);
        wz[1] = 0.75f - (fz - 1.0f) * (fz - 1.0f);
        wz[2] = 0.5f * (fz - 0.5f) * (fz - 0.5f);
        const float wxa = wx[a];

        const float u0 = mv0 - (A00 * fx + A01 * fy + A02 * fz) + fa * A00;
        const float u1 = mv1 - (A10 * fx + A11 * fy + A12 * fz) + fa * A10;
        const float u2 = mv2 - (A20 * fx + A21 * fy + A22 * fz) + fa * A20;

#pragma unroll
        for (int bb = 0; bb < 3; bb++) {
            const float fb = (float)bb;
            const float t0 = u0 + fb * A01;
            const float t1 = u1 + fb * A11;
            const float t2 = u2 + fb * A21;
            const float wab = wxa * wy[bb];
#pragma unroll
            for (int cc = 0; cc < 3; cc++) {
                const float fc = (float)cc;
                const float w = wab * wz[cc];
                const int o = bb * 3 + cc;
                acc[o].x += w * (t0 + fc * A02);
                acc[o].y += w * (t1 + fc * A12);
                acc[o].z += w * (t2 + fc * A22);
                acc[o].w += w * P_MASSf;
            }
        }

        q0 = n0; q1 = n1; q2 = n2; q3 = n3;
    }

#pragma unroll
    for (int bb = 0; bb < 3; bb++)
#pragma unroll
        for (int cc = 0; cc < 3; cc++) {
            const int o = bb * 3 + cc;
            float4* gp = &g_grid[c + a * 4096 + bb * 64 + cc];
            asm volatile(
                "red.global.add.v4.f32 [%0], {%1, %2, %3, %4};"
                :: "l"(gp), "f"(acc[o].x), "f"(acc[o].y),
                   "f"(acc[o].z), "f"(acc[o].w)
                : "memory");
        }
}

// ---------------------------------------------------------------------------
__global__ void __launch_bounds__(256) grid_kernel() {
    int n = blockIdx.x * 256 + threadIdx.x;
    if (n >= GSZ) return;
    float4 g = g_grid[n];
    float vx = 0.f, vy = 0.f, vz = 0.f;
    if (g.w > 0.0f) {
        const float inv = 1.0f / fmaxf(g.w, 1e-10f);
        vx = g.x * inv;
        vy = g.y * inv + DTf * (-9.8f);
        vz = g.z * inv;
    }
    const int i = n >> 12;
    const int j = (n >> 6) & 63;
    const int k = n & 63;
    if ((i < 3 && vx < 0.f) || (i >= NG - 3 && vx > 0.f)) vx = 0.f;
    if ((j < 3 && vy < 0.f) || (j >= NG - 3 && vy > 0.f)) vy = 0.f;
    if ((k < 3 && vz < 0.f) || (k >= NG - 3 && vz > 0.f)) vz = 0.f;
    g_grid[n] = make_float4(vx, vy, vz, 0.f);
}

// ---------------------------------------------------------------------------
// Sorted G2P: gather 27 grid nodes (warp-local addresses), write (v',C')
// coalesced to g_outbuf:
//  o0=(v0,v1,v2,C00) o1=(C01,C02,C10,C11) o2=(C12,C20,C21,C22)
__global__ void __launch_bounds__(256) g2p_kernel() {
    int i = blockIdx.x * 256 + threadIdx.x;
    if (i >= NP) return;
    const float4 q0 = __ldg(&g_pk[4 * i]);
    const float px = q0.x, py = q0.y, pz = q0.z;

    const float gx = px * INV_DXf, gy = py * INV_DXf, gz = pz * INV_DXf;
    const int bx = clampi((int)floorf(gx - 0.5f), 0, NG - 3);
    const int by = clampi((int)floorf(gy - 0.5f), 0, NG - 3);
    const int bz = clampi((int)floorf(gz - 0.5f), 0, NG - 3);
    const float fx = gx - (float)bx, fy = gy - (float)by, fz = gz - (float)bz;

    float wx[3], wy[3], wz[3];
    wx[0] = 0.5f * (1.5f - fx) * (1.5f - fx);
    wx[1] = 0.75f - (fx - 1.0f) * (fx - 1.0f);
    wx[2] = 0.5f * (fx - 0.5f) * (fx - 0.5f);
    wy[0] = 0.5f * (1.5f - fy) * (1.5f - fy);
    wy[1] = 0.75f - (fy - 1.0f) * (fy - 1.0f);
    wy[2] = 0.5f * (fy - 0.5f) * (fy - 0.5f);
    wz[0] = 0.5f * (1.5f - fz) * (1.5f - fz);
    wz[1] = 0.75f - (fz - 1.0f) * (fz - 1.0f);
    wz[2] = 0.5f * (fz - 0.5f) * (fz - 0.5f);

    float vn0 = 0.f, vn1 = 0.f, vn2 = 0.f;
    float B[3][3] = {{0.f,0.f,0.f},{0.f,0.f,0.f},{0.f,0.f,0.f}};

#pragma unroll
    for (int a = 0; a < 3; a++) {
        const float dpi = (float)a - fx;
#pragma unroll
        for (int b = 0; b < 3; b++) {
            const float dpj = (float)b - fy;
            const float wab = wx[a] * wy[b];
            const int rowbase = ((bx + a) * NG + (by + b)) * NG + bz;
#pragma unroll
            for (int k = 0; k < 3; k++) {
                const float dpk = (float)k - fz;
                const float w = wab * wz[k];
                const float4 g = __ldg(&g_grid[rowbase + k]);
                vn0 += w * g.x; vn1 += w * g.y; vn2 += w * g.z;
                B[0][0] += w * g.x * dpi; B[0][1] += w * g.x * dpj; B[0][2] += w * g.x * dpk;
                B[1][0] += w * g.y * dpi; B[1][1] += w * g.y * dpj; B[1][2] += w * g.y * dpk;
                B[2][0] += w * g.z * dpi; B[2][1] += w * g.z * dpj; B[2][2] += w * g.z * dpk;
            }
        }
    }

    float4* dst = &g_outbuf[3 * i];
    dst[0] = make_float4(vn0, vn1, vn2, C_COEF * B[0][0]);
    dst[1] = make_float4(C_COEF * B[0][1], C_COEF * B[0][2],
                         C_COEF * B[1][0], C_COEF * B[1][1]);
    dst[2] = make_float4(C_COEF * B[1][2], C_COEF * B[2][0],
                         C_COEF * B[2][1], C_COEF * B[2][2]);
}

// ---------------------------------------------------------------------------
// Final: original order. Gather (v',C') via slot, read x/F coalesced,
// compute x', F_next, write everything coalesced (+ zero grid for next run).
__global__ void __launch_bounds__(256) final_kernel(
    const float* __restrict__ x, const float* __restrict__ F,
    float* __restrict__ out)
{
    int p = blockIdx.x * 256 + threadIdx.x;
    if (p < GSZ) g_grid[p] = make_float4(0.f, 0.f, 0.f, 0.f);
    if (p >= NP) return;
    const int s = g_slot[p];
    const float4* src = &g_outbuf[3 * s];
    const float4 o0 = __ldg(&src[0]);
    const float4 o1 = __ldg(&src[1]);
    const float4 o2 = __ldg(&src[2]);

    const float vn0 = o0.x, vn1 = o0.y, vn2 = o0.z;

    __stcs(&out[3 * p + 0], x[3 * p + 0] + DTf * vn0);
    __stcs(&out[3 * p + 1], x[3 * p + 1] + DTf * vn1);
    __stcs(&out[3 * p + 2], x[3 * p + 2] + DTf * vn2);
    float* ov = out + (size_t)3 * NP;
    __stcs(&ov[3 * p + 0], vn0);
    __stcs(&ov[3 * p + 1], vn1);
    __stcs(&ov[3 * p + 2], vn2);

    const float Cn[3][3] = {{o0.w, o1.x, o1.y},
                            {o1.z, o1.w, o2.x},
                            {o2.y, o2.z, o2.w}};
    float* oc = out + (size_t)6 * NP;
    __stcs(&oc[9 * p + 0], Cn[0][0]); __stcs(&oc[9 * p + 1], Cn[0][1]);
    __stcs(&oc[9 * p + 2], Cn[0][2]); __stcs(&oc[9 * p + 3], Cn[1][0]);
    __stcs(&oc[9 * p + 4], Cn[1][1]); __stcs(&oc[9 * p + 5], Cn[1][2]);
    __stcs(&oc[9 * p + 6], Cn[2][0]); __stcs(&oc[9 * p + 7], Cn[2][1]);
    __stcs(&oc[9 * p + 8], Cn[2][2]);

    float Fin[3][3];
#pragma unroll
    for (int r = 0; r < 3; r++)
#pragma unroll
        for (int cjj = 0; cjj < 3; cjj++)
            Fin[r][cjj] = __ldcs(&F[9 * p + 3 * r + cjj]);

    float* of = out + (size_t)15 * NP;
#pragma unroll
    for (int r = 0; r < 3; r++) {
        const float m0 = (r == 0 ? 1.f : 0.f) + DTf * Cn[r][0];
        const float m1 = (r == 1 ? 1.f : 0.f) + DTf * Cn[r][1];
        const float m2 = (r == 2 ? 1.f : 0.f) + DTf * Cn[r][2];
#pragma unroll
        for (int cjj = 0; cjj < 3; cjj++)
            __stcs(&of[9 * p + 3 * r + cjj],
                   m0 * Fin[0][cjj] + m1 * Fin[1][cjj] + m2 * Fin[2][cjj]);
    }
}

// ---------------------------------------------------------------------------
extern "C" void kernel_launch(void* const* d_in, const int* in_sizes, int n_in,
                              void* d_out, int out_size)
{
    const float* x      = (const float*)d_in[0];
    const float* v      = (const float*)d_in[1];
    const float* C      = (const float*)d_in[2];
    const float* F      = (const float*)d_in[3];
    const float* stress = (const float*)d_in[4];
    float* out = (float*)d_out;

    const int gblocks = (GSZ + 255) / 256;
    const int pblocks = (NP + 255) / 256;

    hist_kernel<<<pblocks, 256>>>(x);
    scan1_kernel<<<SCAN_BLOCKS, SCAN_T>>>();
    scan23_kernel<<<SCAN_BLOCKS, SCAN_T>>>();
    scatter_kernel<<<pblocks, 256>>>(x, v, C, stress);
    p2g_cell_kernel<<<(3 * GSZ + 255) / 256, 256>>>();
    grid_kernel<<<gblocks, 256>>>();
    g2p_kernel<<<pblocks, 256>>>();
    final_kernel<<<pblocks, 256>>>(x, F, out);
}

// round 11
// speedup vs baseline: 1.1757x; 1.1757x over previous
#include <cuda_runtime.h>

// ---------------------------------------------------------------------------
// MLS-MPM single step, 500k particles, 64^3 grid — sorted pipeline v10.
//   hist(staged x, rank-pack) -> scan1 -> scan23(+zero count, sentinel)
//   -> scatter (smem-staged reads, single 64B record write)
//   -> per-cell P2G (1 thread/cell, prefetch, red.v4)  [round-9 form]
//   -> grid -> sorted G2P -> final(staged F/x in, staged outputs, zero grid).
// ---------------------------------------------------------------------------

namespace {
constexpr int   NG      = 64;
constexpr int   GSZ     = NG * NG * NG;        // 262144
constexpr int   NP      = 500000;
constexpr float INV_DXf = 64.0f;
constexpr float DXf     = 1.0f / 64.0f;
constexpr float DTf     = 5e-4f;
constexpr float P_MASSf = 4.76837158203125e-4f;   // 1000 * (DX/2)^3
constexpr float AFF_COEF = -3.90625e-6f;          // -DT*P_VOL*4*INV_DX^2
constexpr float C_COEF   = 256.0f;                // 4*INV_DX^2*DX
constexpr int   SCAN_T      = 256;
constexpr int   SCAN_BLOCKS = 256;                // 256 blocks * 1024 elems
}

__device__ float4 g_grid[GSZ];                    // (mv.xyz, m) -> (v.xyz, 0)
__device__ __align__(16) int g_count[GSZ];
__device__ __align__(16) int g_start[GSZ + 4];    // exclusive offsets + sentinel
__device__ int    g_bsum[SCAN_BLOCKS];
__device__ int    g_binid[NP];                    // bin | rank<<18
__device__ int    g_slot[NP];                     // original p -> sorted slot
__device__ __align__(64) float4 g_pk[4 * NP];     // 64B payload records  32 MB
__device__ float4 g_outbuf[3 * NP];               // (v',C')              24 MB

// ---------------------------------------------------------------------------
__device__ __forceinline__ int clampi(int v, int lo, int hi) {
    return v < lo ? lo : (v > hi ? hi : v);
}

// hist: staged coalesced x read; bin count + rank via atomic return.
__global__ void __launch_bounds__(256) hist_kernel(const float* __restrict__ x) {
    __shared__ float hx[768];
    const int tid   = threadIdx.x;
    const int pbase = blockIdx.x * 256;

    if (pbase + 256 <= NP) {
        const float4* x4 = reinterpret_cast<const float4*>(x + 3 * pbase);
        if (tid < 192) reinterpret_cast<float4*>(hx)[tid] = __ldg(&x4[tid]);
    } else {
        const int nfl3 = (NP - pbase) * 3;
        for (int i = tid; i < nfl3; i += 256) hx[i] = x[3 * pbase + i];
    }
    __syncthreads();

    const int p = pbase + tid;
    if (p >= NP) return;
    const float gx = hx[3 * tid + 0] * INV_DXf;
    const float gy = hx[3 * tid + 1] * INV_DXf;
    const float gz = hx[3 * tid + 2] * INV_DXf;
    const int bx = clampi((int)floorf(gx - 0.5f), 0, NG - 3);
    const int by = clampi((int)floorf(gy - 0.5f), 0, NG - 3);
    const int bz = clampi((int)floorf(gz - 0.5f), 0, NG - 3);
    const int bin = (bx * NG + by) * NG + bz;
    const int rank = atomicAdd(&g_count[bin], 1);
    g_binid[p] = bin | (rank << 18);
}

// ---------------------------------------------------------------------------
// scan1: per-block (1024 elems) exclusive scan into g_start, totals to g_bsum.
__global__ void __launch_bounds__(SCAN_T) scan1_kernel() {
    __shared__ int sh[SCAN_T];
    const int t = threadIdx.x, b = blockIdx.x;
    const int4 cv = reinterpret_cast<const int4*>(g_count)[b * SCAN_T + t];
    const int ts = cv.x + cv.y + cv.z + cv.w;
    sh[t] = ts;
    __syncthreads();
#pragma unroll
    for (int off = 1; off < SCAN_T; off <<= 1) {
        int a = (t >= off) ? sh[t - off] : 0;
        __syncthreads();
        sh[t] += a;
        __syncthreads();
    }
    const int excl = sh[t] - ts;
    int4 ov;
    ov.x = excl;
    ov.y = excl + cv.x;
    ov.z = excl + cv.x + cv.y;
    ov.w = excl + cv.x + cv.y + cv.z;
    reinterpret_cast<int4*>(g_start)[b * SCAN_T + t] = ov;
    if (t == SCAN_T - 1) g_bsum[b] = sh[t];
}

// scan23: block b adds sum(g_bsum[0..b)) to its 1024 elements; writes g_start;
// zeroes g_count (consumed) and writes the sentinel.
__global__ void __launch_bounds__(SCAN_T) scan23_kernel() {
    __shared__ int red[SCAN_T];
    const int t = threadIdx.x, b = blockIdx.x;
    red[t] = (t < b) ? g_bsum[t] : 0;
    __syncthreads();
#pragma unroll
    for (int off = SCAN_T / 2; off > 0; off >>= 1) {
        if (t < off) red[t] += red[t + off];
        __syncthreads();
    }
    const int offset = red[0];
    const int idx = b * SCAN_T + t;
    int4 sv = reinterpret_cast<const int4*>(g_start)[idx];
    sv.x += offset; sv.y += offset; sv.z += offset; sv.w += offset;
    reinterpret_cast<int4*>(g_start)[idx] = sv;
    reinterpret_cast<int4*>(g_count)[idx] = make_int4(0, 0, 0, 0);
    if (b == SCAN_BLOCKS - 1 && t == SCAN_T - 1) g_start[GSZ] = NP;
}

// ---------------------------------------------------------------------------
// Scatter: smem-staged coalesced input reads; one 64B record write per
// particle at sorted slot s = g_start[bin] + rank.
__global__ void __launch_bounds__(256) scatter_kernel(
    const float* __restrict__ x, const float* __restrict__ v,
    const float* __restrict__ C, const float* __restrict__ S)
{
    __shared__ float sx[768];
    __shared__ float sv_[768];
    __shared__ float sC[2304];
    __shared__ float sS[2304];

    const int tid   = threadIdx.x;
    const int pbase = blockIdx.x * 256;

    if (pbase + 256 <= NP) {
        const float4* x4 = reinterpret_cast<const float4*>(x + 3 * pbase);
        const float4* v4 = reinterpret_cast<const float4*>(v + 3 * pbase);
        const float4* C4 = reinterpret_cast<const float4*>(C + 9 * pbase);
        const float4* S4 = reinterpret_cast<const float4*>(S + 9 * pbase);
        if (tid < 192) {
            reinterpret_cast<float4*>(sx)[tid]  = __ldcs(&x4[tid]);
            reinterpret_cast<float4*>(sv_)[tid] = __ldcs(&v4[tid]);
        }
#pragma unroll
        for (int i = tid; i < 576; i += 256) {
            reinterpret_cast<float4*>(sC)[i] = __ldcs(&C4[i]);
            reinterpret_cast<float4*>(sS)[i] = __ldcs(&S4[i]);
        }
    } else {
        const int nfl3 = (NP - pbase) * 3;
        const int nfl9 = (NP - pbase) * 9;
        for (int i = tid; i < nfl3; i += 256) {
            sx[i]  = x[3 * pbase + i];
            sv_[i] = v[3 * pbase + i];
        }
        for (int i = tid; i < nfl9; i += 256) {
            sC[i] = C[9 * pbase + i];
            sS[i] = S[9 * pbase + i];
        }
    }
    __syncthreads();

    const int p = pbase + tid;
    if (p >= NP) return;

    const int pk  = g_binid[p];
    const int bin = pk & 0x3FFFF;
    const int s   = __ldg(&g_start[bin]) + (pk >> 18);
    g_slot[p] = s;

    float A[9];
#pragma unroll
    for (int i = 0; i < 9; i++)
        A[i] = (sS[9 * tid + i] * AFF_COEF + P_MASSf * sC[9 * tid + i]) * DXf;
    const float mv0 = P_MASSf * sv_[3 * tid + 0];
    const float mv1 = P_MASSf * sv_[3 * tid + 1];
    const float mv2 = P_MASSf * sv_[3 * tid + 2];

    float4* r = &g_pk[4 * s];
    r[0] = make_float4(sx[3 * tid + 0], sx[3 * tid + 1], sx[3 * tid + 2], mv0);
    r[1] = make_float4(mv1, mv2, A[0], A[1]);
    r[2] = make_float4(A[2], A[3], A[4], A[5]);
    r[3] = make_float4(A[6], A[7], A[8], 0.f);
}

// ---------------------------------------------------------------------------
// Per-cell P2G (round-9 form): one thread = one grid cell; prefetch payload,
// accumulate 27 node contributions in registers, then 27 red.v4.
__global__ void __launch_bounds__(128) p2g_cell_kernel() {
    const int c = blockIdx.x * 128 + threadIdx.x;
    if (c >= GSZ) return;
    const int s0 = g_start[c];
    const int s1 = g_start[c + 1];
    if (s0 >= s1) return;

    const float bi = (float)(c >> 12);
    const float bj = (float)((c >> 6) & 63);
    const float bk = (float)(c & 63);

    float4 acc[27];
#pragma unroll
    for (int o = 0; o < 27; o++) acc[o] = make_float4(0.f, 0.f, 0.f, 0.f);

    float4 q0 = __ldg(&g_pk[4 * s0 + 0]);
    float4 q1 = __ldg(&g_pk[4 * s0 + 1]);
    float4 q2 = __ldg(&g_pk[4 * s0 + 2]);
    float4 q3 = __ldg(&g_pk[4 * s0 + 3]);

    for (int t = s0; t < s1; ++t) {
        float4 n0, n1, n2, n3;
        const int tn = t + 1;
        if (tn < s1) {
            n0 = __ldg(&g_pk[4 * tn + 0]);
            n1 = __ldg(&g_pk[4 * tn + 1]);
            n2 = __ldg(&g_pk[4 * tn + 2]);
            n3 = __ldg(&g_pk[4 * tn + 3]);
        }

        const float fx = q0.x * INV_DXf - bi;
        const float fy = q0.y * INV_DXf - bj;
        const float fz = q0.z * INV_DXf - bk;
        const float mv0 = q0.w, mv1 = q1.x, mv2 = q1.y;
        const float A00 = q1.z, A01 = q1.w, A02 = q2.x;
        const float A10 = q2.y, A11 = q2.z, A12 = q2.w;
        const float A20 = q3.x, A21 = q3.y, A22 = q3.z;

        float wx[3], wy[3], wz[3];
        wx[0] = 0.5f * (1.5f - fx) * (1.5f - fx);
        wx[1] = 0.75f - (fx - 1.0f) * (fx - 1.0f);
        wx[2] = 0.5f * (fx - 0.5f) * (fx - 0.5f);
        wy[0] = 0.5f * (1.5f - fy) * (1.5f - fy);
        wy[1] = 0.75f - (fy - 1.0f) * (fy - 1.0f);
        wy[2] = 0.5f * (fy - 0.5f) * (fy - 0.5f);
        wz[0] = 0.5f * (1.5f - fz) * (1.5f - fz);
        wz[1] = 0.75f - (fz - 1.0f) * (fz - 1.0f);
        wz[2] = 0.5f * (fz - 0.5f) * (fz - 0.5f);

        const float b0 = mv0 - (A00 * fx + A01 * fy + A02 * fz);
        const float b1 = mv1 - (A10 * fx + A11 * fy + A12 * fz);
        const float b2 = mv2 - (A20 * fx + A21 * fy + A22 * fz);

#pragma unroll
        for (int a = 0; a < 3; a++) {
            const float fa = (float)a;
            const float u0 = b0 + fa * A00;
            const float u1 = b1 + fa * A10;
            const float u2 = b2 + fa * A20;
#pragma unroll
            for (int bb = 0; bb < 3; bb++) {
                const float fb = (float)bb;
                const float t0 = u0 + fb * A01;
                const float t1 = u1 + fb * A11;
                const float t2 = u2 + fb * A21;
                const float wab = wx[a] * wy[bb];
#pragma unroll
                for (int cc = 0; cc < 3; cc++) {
                    const float fc = (float)cc;
                    const float w = wab * wz[cc];
                    const int o = a * 9 + bb * 3 + cc;
                    acc[o].x += w * (t0 + fc * A02);
                    acc[o].y += w * (t1 + fc * A12);
                    acc[o].z += w * (t2 + fc * A22);
                    acc[o].w += w * P_MASSf;
                }
            }
        }

        q0 = n0; q1 = n1; q2 = n2; q3 = n3;
    }

#pragma unroll
    for (int a = 0; a < 3; a++)
#pragma unroll
        for (int bb = 0; bb < 3; bb++)
#pragma unroll
            for (int cc = 0; cc < 3; cc++) {
                const int o = a * 9 + bb * 3 + cc;
                float4* gp = &g_grid[c + a * 4096 + bb * 64 + cc];
                asm volatile(
                    "red.global.add.v4.f32 [%0], {%1, %2, %3, %4};"
                    :: "l"(gp), "f"(acc[o].x), "f"(acc[o].y),
                       "f"(acc[o].z), "f"(acc[o].w)
                    : "memory");
            }
}

// ---------------------------------------------------------------------------
__global__ void __launch_bounds__(256) grid_kernel() {
    int n = blockIdx.x * 256 + threadIdx.x;
    if (n >= GSZ) return;
    float4 g = g_grid[n];
    float vx = 0.f, vy = 0.f, vz = 0.f;
    if (g.w > 0.0f) {
        const float inv = 1.0f / fmaxf(g.w, 1e-10f);
        vx = g.x * inv;
        vy = g.y * inv + DTf * (-9.8f);
        vz = g.z * inv;
    }
    const int i = n >> 12;
    const int j = (n >> 6) & 63;
    const int k = n & 63;
    if ((i < 3 && vx < 0.f) || (i >= NG - 3 && vx > 0.f)) vx = 0.f;
    if ((j < 3 && vy < 0.f) || (j >= NG - 3 && vy > 0.f)) vy = 0.f;
    if ((k < 3 && vz < 0.f) || (k >= NG - 3 && vz > 0.f)) vz = 0.f;
    g_grid[n] = make_float4(vx, vy, vz, 0.f);
}

// ---------------------------------------------------------------------------
// Sorted G2P: gather 27 grid nodes (warp-local addresses), write (v',C')
// coalesced to g_outbuf:
//  o0=(v0,v1,v2,C00) o1=(C01,C02,C10,C11) o2=(C12,C20,C21,C22)
__global__ void __launch_bounds__(256) g2p_kernel() {
    int i = blockIdx.x * 256 + threadIdx.x;
    if (i >= NP) return;
    const float4 q0 = __ldg(&g_pk[4 * i]);
    const float px = q0.x, py = q0.y, pz = q0.z;

    const float gx = px * INV_DXf, gy = py * INV_DXf, gz = pz * INV_DXf;
    const int bx = clampi((int)floorf(gx - 0.5f), 0, NG - 3);
    const int by = clampi((int)floorf(gy - 0.5f), 0, NG - 3);
    const int bz = clampi((int)floorf(gz - 0.5f), 0, NG - 3);
    const float fx = gx - (float)bx, fy = gy - (float)by, fz = gz - (float)bz;

    float wx[3], wy[3], wz[3];
    wx[0] = 0.5f * (1.5f - fx) * (1.5f - fx);
    wx[1] = 0.75f - (fx - 1.0f) * (fx - 1.0f);
    wx[2] = 0.5f * (fx - 0.5f) * (fx - 0.5f);
    wy[0] = 0.5f * (1.5f - fy) * (1.5f - fy);
    wy[1] = 0.75f - (fy - 1.0f) * (fy - 1.0f);
    wy[2] = 0.5f * (fy - 0.5f) * (fy - 0.5f);
    wz[0] = 0.5f * (1.5f - fz) * (1.5f - fz);
    wz[1] = 0.75f - (fz - 1.0f) * (fz - 1.0f);
    wz[2] = 0.5f * (fz - 0.5f) * (fz - 0.5f);

    float vn0 = 0.f, vn1 = 0.f, vn2 = 0.f;
    float B[3][3] = {{0.f,0.f,0.f},{0.f,0.f,0.f},{0.f,0.f,0.f}};

#pragma unroll
    for (int a = 0; a < 3; a++) {
        const float dpi = (float)a - fx;
#pragma unroll
        for (int b = 0; b < 3; b++) {
            const float dpj = (float)b - fy;
            const float wab = wx[a] * wy[b];
            const int rowbase = ((bx + a) * NG + (by + b)) * NG + bz;
#pragma unroll
            for (int k = 0; k < 3; k++) {
                const float dpk = (float)k - fz;
                const float w = wab * wz[k];
                const float4 g = __ldg(&g_grid[rowbase + k]);
                vn0 += w * g.x; vn1 += w * g.y; vn2 += w * g.z;
                B[0][0] += w * g.x * dpi; B[0][1] += w * g.x * dpj; B[0][2] += w * g.x * dpk;
                B[1][0] += w * g.y * dpi; B[1][1] += w * g.y * dpj; B[1][2] += w * g.y * dpk;
                B[2][0] += w * g.z * dpi; B[2][1] += w * g.z * dpj; B[2][2] += w * g.z * dpk;
            }
        }
    }

    float4* dst = &g_outbuf[3 * i];
    dst[0] = make_float4(vn0, vn1, vn2, C_COEF * B[0][0]);
    dst[1] = make_float4(C_COEF * B[0][1], C_COEF * B[0][2],
                         C_COEF * B[1][0], C_COEF * B[1][1]);
    dst[2] = make_float4(C_COEF * B[1][2], C_COEF * B[2][0],
                         C_COEF * B[2][1], C_COEF * B[2][2]);
}

// ---------------------------------------------------------------------------
// Final: original order. Gather (v',C') via slot; F and x staged in via
// coalesced float4; ALL outputs staged through smem and written as float4.
// Also zeroes g_grid for the next run.
__global__ void __launch_bounds__(256) final_kernel(
    const float* __restrict__ x, const float* __restrict__ F,
    float* __restrict__ out)
{
    __shared__ float sxi[768];    // x in
    __shared__ float sFi[2304];   // F in
    __shared__ float ox_[768];    // x' out
    __shared__ float ov_[768];    // v' out
    __shared__ float oC_[2304];   // C' out
    __shared__ float oF_[2304];   // F' out

    const int tid   = threadIdx.x;
    const int pbase = blockIdx.x * 256;
    const int gid   = pbase + tid;
    if (gid < GSZ) g_grid[gid] = make_float4(0.f, 0.f, 0.f, 0.f);

    const bool full = (pbase + 256 <= NP);
    if (full) {
        const float4* x4 = reinterpret_cast<const float4*>(x + 3 * pbase);
        const float4* F4 = reinterpret_cast<const float4*>(F + 9 * pbase);
        if (tid < 192) reinterpret_cast<float4*>(sxi)[tid] = __ldcs(&x4[tid]);
#pragma unroll
        for (int i = tid; i < 576; i += 256)
            reinterpret_cast<float4*>(sFi)[i] = __ldcs(&F4[i]);
    } else {
        const int nfl3 = (NP > pbase) ? (NP - pbase) * 3 : 0;
        const int nfl9 = (NP > pbase) ? (NP - pbase) * 9 : 0;
        for (int i = tid; i < nfl3; i += 256) sxi[i] = x[3 * pbase + i];
        for (int i = tid; i < nfl9; i += 256) sFi[i] = F[9 * pbase + i];
    }
    __syncthreads();

    const int p = gid;
    if (p < NP) {
        const int s = g_slot[p];
        const float4* src = &g_outbuf[3 * s];
        const float4 o0 = __ldg(&src[0]);
        const float4 o1 = __ldg(&src[1]);
        const float4 o2 = __ldg(&src[2]);

        const float vn0 = o0.x, vn1 = o0.y, vn2 = o0.z;
        ox_[3 * tid + 0] = sxi[3 * tid + 0] + DTf * vn0;
        ox_[3 * tid + 1] = sxi[3 * tid + 1] + DTf * vn1;
        ox_[3 * tid + 2] = sxi[3 * tid + 2] + DTf * vn2;
        ov_[3 * tid + 0] = vn0;
        ov_[3 * tid + 1] = vn1;
        ov_[3 * tid + 2] = vn2;

        const float Cn[3][3] = {{o0.w, o1.x, o1.y},
                                {o1.z, o1.w, o2.x},
                                {o2.y, o2.z, o2.w}};
#pragma unroll
        for (int r = 0; r < 3; r++)
#pragma unroll
            for (int cjj = 0; cjj < 3; cjj++)
                oC_[9 * tid + 3 * r + cjj] = Cn[r][cjj];

#pragma unroll
        for (int r = 0; r < 3; r++) {
            const float m0 = (r == 0 ? 1.f : 0.f) + DTf * Cn[r][0];
            const float m1 = (r == 1 ? 1.f : 0.f) + DTf * Cn[r][1];
            const float m2 = (r == 2 ? 1.f : 0.f) + DTf * Cn[r][2];
#pragma unroll
            for (int cjj = 0; cjj < 3; cjj++)
                oF_[9 * tid + 3 * r + cjj] =
                    m0 * sFi[9 * tid + 0 + cjj] +
                    m1 * sFi[9 * tid + 3 + cjj] +
                    m2 * sFi[9 * tid + 6 + cjj];
        }
    }
    __syncthreads();

    if (full) {
        float4* dx = reinterpret_cast<float4*>(out + (size_t)3 * pbase);
        float4* dv = reinterpret_cast<float4*>(out + (size_t)3 * NP + 3 * pbase);
        float4* dC = reinterpret_cast<float4*>(out + (size_t)6 * NP + 9 * pbase);
        float4* dF = reinterpret_cast<float4*>(out + (size_t)15 * NP + 9 * pbase);
        if (tid < 192) {
            __stcs(&dx[tid], reinterpret_cast<float4*>(ox_)[tid]);
            __stcs(&dv[tid], reinterpret_cast<float4*>(ov_)[tid]);
        }
#pragma unroll
        for (int i = tid; i < 576; i += 256) {
            __stcs(&dC[i], reinterpret_cast<float4*>(oC_)[i]);
            __stcs(&dF[i], reinterpret_cast<float4*>(oF_)[i]);
        }
    } else if (pbase < NP) {
        const int nfl3 = (NP - pbase) * 3;
        const int nfl9 = (NP - pbase) * 9;
        for (int i = tid; i < nfl3; i += 256) {
            out[3 * pbase + i] = ox_[i];
            out[(size_t)3 * NP + 3 * pbase + i] = ov_[i];
        }
        for (int i = tid; i < nfl9; i += 256) {
            out[(size_t)6 * NP + 9 * pbase + i] = oC_[i];
            out[(size_t)15 * NP + 9 * pbase + i] = oF_[i];
        }
    }
}

// ---------------------------------------------------------------------------
extern "C" void kernel_launch(void* const* d_in, const int* in_sizes, int n_in,
                              void* d_out, int out_size)
{
    const float* x      = (const float*)d_in[0];
    const float* v      = (const float*)d_in[1];
    const float* C      = (const float*)d_in[2];
    const float* F      = (const float*)d_in[3];
    const float* stress = (const float*)d_in[4];
    float* out = (float*)d_out;

    const int gblocks = (GSZ + 255) / 256;
    const int pblocks = (NP + 255) / 256;

    hist_kernel<<<pblocks, 256>>>(x);
    scan1_kernel<<<SCAN_BLOCKS, SCAN_T>>>();
    scan23_kernel<<<SCAN_BLOCKS, SCAN_T>>>();
    scatter_kernel<<<pblocks, 256>>>(x, v, C, stress);
    p2g_cell_kernel<<<(GSZ + 127) / 128, 128>>>();
    grid_kernel<<<gblocks, 256>>>();
    g2p_kernel<<<pblocks, 256>>>();
    final_kernel<<<pblocks, 256>>>(x, F, out);
}

// round 12
// speedup vs baseline: 1.2230x; 1.0403x over previous
#include <cuda_runtime.h>

// ---------------------------------------------------------------------------
// MLS-MPM single step, 500k particles, 64^3 grid — sorted pipeline v11.
//   hist(staged x, rank-pack, reset ncell) -> scan1(+occupied-cell compaction)
//   -> scan23(+zero count, sentinel) -> scatter (staged reads, 64B record)
//   -> per-cell P2G over COMPACTED cell list (prefetch, red.v4)
//   -> grid(skip-empty writes) -> sorted G2P
//   -> final(staged F/x in, staged outputs, zero grid).
// ---------------------------------------------------------------------------

namespace {
constexpr int   NG      = 64;
constexpr int   GSZ     = NG * NG * NG;        // 262144
constexpr int   NP      = 500000;
constexpr float INV_DXf = 64.0f;
constexpr float DXf     = 1.0f / 64.0f;
constexpr float DTf     = 5e-4f;
constexpr float P_MASSf = 4.76837158203125e-4f;   // 1000 * (DX/2)^3
constexpr float AFF_COEF = -3.90625e-6f;          // -DT*P_VOL*4*INV_DX^2
constexpr float C_COEF   = 256.0f;                // 4*INV_DX^2*DX
constexpr int   SCAN_T      = 256;
constexpr int   SCAN_BLOCKS = 256;                // 256 blocks * 1024 elems
}

__device__ float4 g_grid[GSZ];                    // (mv.xyz, m) -> (v.xyz, 0)
__device__ __align__(16) int g_count[GSZ];
__device__ __align__(16) int g_start[GSZ + 4];    // exclusive offsets + sentinel
__device__ int    g_bsum[SCAN_BLOCKS];
__device__ int    g_binid[NP];                    // bin | rank<<18
__device__ int    g_slot[NP];                     // original p -> sorted slot
__device__ int    g_ncell;                        // # occupied cells
__device__ int    g_cellidx[GSZ];                 // compacted occupied cells
__device__ __align__(64) float4 g_pk[4 * NP];     // 64B payload records  32 MB
__device__ float4 g_outbuf[3 * NP];               // (v',C')              24 MB

// ---------------------------------------------------------------------------
__device__ __forceinline__ int clampi(int v, int lo, int hi) {
    return v < lo ? lo : (v > hi ? hi : v);
}

// hist: staged coalesced x read; bin count + rank via atomic return.
__global__ void __launch_bounds__(256) hist_kernel(const float* __restrict__ x) {
    __shared__ float hx[768];
    const int tid   = threadIdx.x;
    const int pbase = blockIdx.x * 256;
    if (blockIdx.x == 0 && tid == 0) g_ncell = 0;

    if (pbase + 256 <= NP) {
        const float4* x4 = reinterpret_cast<const float4*>(x + 3 * pbase);
        if (tid < 192) reinterpret_cast<float4*>(hx)[tid] = __ldg(&x4[tid]);
    } else {
        const int nfl3 = (NP - pbase) * 3;
        for (int i = tid; i < nfl3; i += 256) hx[i] = x[3 * pbase + i];
    }
    __syncthreads();

    const int p = pbase + tid;
    if (p >= NP) return;
    const float gx = hx[3 * tid + 0] * INV_DXf;
    const float gy = hx[3 * tid + 1] * INV_DXf;
    const float gz = hx[3 * tid + 2] * INV_DXf;
    const int bx = clampi((int)floorf(gx - 0.5f), 0, NG - 3);
    const int by = clampi((int)floorf(gy - 0.5f), 0, NG - 3);
    const int bz = clampi((int)floorf(gz - 0.5f), 0, NG - 3);
    const int bin = (bx * NG + by) * NG + bz;
    const int rank = atomicAdd(&g_count[bin], 1);
    g_binid[p] = bin | (rank << 18);
}

// ---------------------------------------------------------------------------
// scan1: per-block (1024 elems) exclusive scan into g_start, totals to g_bsum.
// Also compacts occupied cell indices into g_cellidx (1 atomic per block).
__global__ void __launch_bounds__(SCAN_T) scan1_kernel() {
    __shared__ int sh[SCAN_T];
    __shared__ int so[SCAN_T];
    __shared__ int sbase;
    const int t = threadIdx.x, b = blockIdx.x;
    const int4 cv = reinterpret_cast<const int4*>(g_count)[b * SCAN_T + t];
    const int ts = cv.x + cv.y + cv.z + cv.w;
    const int nocc = (cv.x > 0) + (cv.y > 0) + (cv.z > 0) + (cv.w > 0);
    sh[t] = ts;
    so[t] = nocc;
    __syncthreads();
#pragma unroll
    for (int off = 1; off < SCAN_T; off <<= 1) {
        int a  = (t >= off) ? sh[t - off] : 0;
        int a2 = (t >= off) ? so[t - off] : 0;
        __syncthreads();
        sh[t] += a;
        so[t] += a2;
        __syncthreads();
    }
    const int excl = sh[t] - ts;
    int4 ov;
    ov.x = excl;
    ov.y = excl + cv.x;
    ov.z = excl + cv.x + cv.y;
    ov.w = excl + cv.x + cv.y + cv.z;
    reinterpret_cast<int4*>(g_start)[b * SCAN_T + t] = ov;
    if (t == SCAN_T - 1) {
        g_bsum[b] = sh[t];
        sbase = atomicAdd(&g_ncell, so[t]);
    }
    __syncthreads();
    // append this thread's occupied cells
    int w = sbase + so[t] - nocc;
    const int cbase = (b * SCAN_T + t) * 4;
    if (cv.x > 0) g_cellidx[w++] = cbase + 0;
    if (cv.y > 0) g_cellidx[w++] = cbase + 1;
    if (cv.z > 0) g_cellidx[w++] = cbase + 2;
    if (cv.w > 0) g_cellidx[w]   = cbase + 3;
}

// scan23: block b adds sum(g_bsum[0..b)) to its 1024 elements; writes g_start;
// zeroes g_count (consumed) and writes the sentinel.
__global__ void __launch_bounds__(SCAN_T) scan23_kernel() {
    __shared__ int red[SCAN_T];
    const int t = threadIdx.x, b = blockIdx.x;
    red[t] = (t < b) ? g_bsum[t] : 0;
    __syncthreads();
#pragma unroll
    for (int off = SCAN_T / 2; off > 0; off >>= 1) {
        if (t < off) red[t] += red[t + off];
        __syncthreads();
    }
    const int offset = red[0];
    const int idx = b * SCAN_T + t;
    int4 sv = reinterpret_cast<const int4*>(g_start)[idx];
    sv.x += offset; sv.y += offset; sv.z += offset; sv.w += offset;
    reinterpret_cast<int4*>(g_start)[idx] = sv;
    reinterpret_cast<int4*>(g_count)[idx] = make_int4(0, 0, 0, 0);
    if (b == SCAN_BLOCKS - 1 && t == SCAN_T - 1) g_start[GSZ] = NP;
}

// ---------------------------------------------------------------------------
// Scatter: smem-staged coalesced input reads; one 64B record write per
// particle at sorted slot s = g_start[bin] + rank.
__global__ void __launch_bounds__(256) scatter_kernel(
    const float* __restrict__ x, const float* __restrict__ v,
    const float* __restrict__ C, const float* __restrict__ S)
{
    __shared__ float sx[768];
    __shared__ float sv_[768];
    __shared__ float sC[2304];
    __shared__ float sS[2304];

    const int tid   = threadIdx.x;
    const int pbase = blockIdx.x * 256;

    if (pbase + 256 <= NP) {
        const float4* x4 = reinterpret_cast<const float4*>(x + 3 * pbase);
        const float4* v4 = reinterpret_cast<const float4*>(v + 3 * pbase);
        const float4* C4 = reinterpret_cast<const float4*>(C + 9 * pbase);
        const float4* S4 = reinterpret_cast<const float4*>(S + 9 * pbase);
        if (tid < 192) {
            reinterpret_cast<float4*>(sx)[tid]  = __ldcs(&x4[tid]);
            reinterpret_cast<float4*>(sv_)[tid] = __ldcs(&v4[tid]);
        }
#pragma unroll
        for (int i = tid; i < 576; i += 256) {
            reinterpret_cast<float4*>(sC)[i] = __ldcs(&C4[i]);
            reinterpret_cast<float4*>(sS)[i] = __ldcs(&S4[i]);
        }
    } else {
        const int nfl3 = (NP - pbase) * 3;
        const int nfl9 = (NP - pbase) * 9;
        for (int i = tid; i < nfl3; i += 256) {
            sx[i]  = x[3 * pbase + i];
            sv_[i] = v[3 * pbase + i];
        }
        for (int i = tid; i < nfl9; i += 256) {
            sC[i] = C[9 * pbase + i];
            sS[i] = S[9 * pbase + i];
        }
    }
    __syncthreads();

    const int p = pbase + tid;
    if (p >= NP) return;

    const int pk  = g_binid[p];
    const int bin = pk & 0x3FFFF;
    const int s   = __ldg(&g_start[bin]) + (pk >> 18);
    g_slot[p] = s;

    float A[9];
#pragma unroll
    for (int i = 0; i < 9; i++)
        A[i] = (sS[9 * tid + i] * AFF_COEF + P_MASSf * sC[9 * tid + i]) * DXf;
    const float mv0 = P_MASSf * sv_[3 * tid + 0];
    const float mv1 = P_MASSf * sv_[3 * tid + 1];
    const float mv2 = P_MASSf * sv_[3 * tid + 2];

    float4* r = &g_pk[4 * s];
    r[0] = make_float4(sx[3 * tid + 0], sx[3 * tid + 1], sx[3 * tid + 2], mv0);
    r[1] = make_float4(mv1, mv2, A[0], A[1]);
    r[2] = make_float4(A[2], A[3], A[4], A[5]);
    r[3] = make_float4(A[6], A[7], A[8], 0.f);
}

// ---------------------------------------------------------------------------
// Per-cell P2G over the compacted occupied-cell list: one thread = one
// occupied cell; prefetch payload, accumulate 27 node sums, 27 red.v4.
__global__ void __launch_bounds__(128) p2g_cell_kernel() {
    const int n = blockIdx.x * 128 + threadIdx.x;
    if (n >= g_ncell) return;
    const int c = g_cellidx[n];
    const int s0 = g_start[c];
    const int s1 = g_start[c + 1];

    const float bi = (float)(c >> 12);
    const float bj = (float)((c >> 6) & 63);
    const float bk = (float)(c & 63);

    float4 acc[27];
#pragma unroll
    for (int o = 0; o < 27; o++) acc[o] = make_float4(0.f, 0.f, 0.f, 0.f);

    float4 q0 = __ldg(&g_pk[4 * s0 + 0]);
    float4 q1 = __ldg(&g_pk[4 * s0 + 1]);
    float4 q2 = __ldg(&g_pk[4 * s0 + 2]);
    float4 q3 = __ldg(&g_pk[4 * s0 + 3]);

    for (int t = s0; t < s1; ++t) {
        float4 n0, n1, n2, n3;
        const int tn = t + 1;
        if (tn < s1) {
            n0 = __ldg(&g_pk[4 * tn + 0]);
            n1 = __ldg(&g_pk[4 * tn + 1]);
            n2 = __ldg(&g_pk[4 * tn + 2]);
            n3 = __ldg(&g_pk[4 * tn + 3]);
        }

        const float fx = q0.x * INV_DXf - bi;
        const float fy = q0.y * INV_DXf - bj;
        const float fz = q0.z * INV_DXf - bk;
        const float mv0 = q0.w, mv1 = q1.x, mv2 = q1.y;
        const float A00 = q1.z, A01 = q1.w, A02 = q2.x;
        const float A10 = q2.y, A11 = q2.z, A12 = q2.w;
        const float A20 = q3.x, A21 = q3.y, A22 = q3.z;

        float wx[3], wy[3], wz[3];
        wx[0] = 0.5f * (1.5f - fx) * (1.5f - fx);
        wx[1] = 0.75f - (fx - 1.0f) * (fx - 1.0f);
        wx[2] = 0.5f * (fx - 0.5f) * (fx - 0.5f);
        wy[0] = 0.5f * (1.5f - fy) * (1.5f - fy);
        wy[1] = 0.75f - (fy - 1.0f) * (fy - 1.0f);
        wy[2] = 0.5f * (fy - 0.5f) * (fy - 0.5f);
        wz[0] = 0.5f * (1.5f - fz) * (1.5f - fz);
        wz[1] = 0.75f - (fz - 1.0f) * (fz - 1.0f);
        wz[2] = 0.5f * (fz - 0.5f) * (fz - 0.5f);

        const float b0 = mv0 - (A00 * fx + A01 * fy + A02 * fz);
        const float b1 = mv1 - (A10 * fx + A11 * fy + A12 * fz);
        const float b2 = mv2 - (A20 * fx + A21 * fy + A22 * fz);

#pragma unroll
        for (int a = 0; a < 3; a++) {
            const float fa = (float)a;
            const float u0 = b0 + fa * A00;
            const float u1 = b1 + fa * A10;
            const float u2 = b2 + fa * A20;
#pragma unroll
            for (int bb = 0; bb < 3; bb++) {
                const float fb = (float)bb;
                const float t0 = u0 + fb * A01;
                const float t1 = u1 + fb * A11;
                const float t2 = u2 + fb * A21;
                const float wab = wx[a] * wy[bb];
#pragma unroll
                for (int cc = 0; cc < 3; cc++) {
                    const float fc = (float)cc;
                    const float w = wab * wz[cc];
                    const int o = a * 9 + bb * 3 + cc;
                    acc[o].x += w * (t0 + fc * A02);
                    acc[o].y += w * (t1 + fc * A12);
                    acc[o].z += w * (t2 + fc * A22);
                    acc[o].w += w * P_MASSf;
                }
            }
        }

        q0 = n0; q1 = n1; q2 = n2; q3 = n3;
    }

#pragma unroll
    for (int a = 0; a < 3; a++)
#pragma unroll
        for (int bb = 0; bb < 3; bb++)
#pragma unroll
            for (int cc = 0; cc < 3; cc++) {
                const int o = a * 9 + bb * 3 + cc;
                float4* gp = &g_grid[c + a * 4096 + bb * 64 + cc];
                asm volatile(
                    "red.global.add.v4.f32 [%0], {%1, %2, %3, %4};"
                    :: "l"(gp), "f"(acc[o].x), "f"(acc[o].y),
                       "f"(acc[o].z), "f"(acc[o].w)
                    : "memory");
            }
}

// ---------------------------------------------------------------------------
// grid: normalize momentum, gravity, boundary. Empty cells are exactly
// (0,0,0,0) already (w==0 => all contributions were 0) — skip the store.
__global__ void __launch_bounds__(256) grid_kernel() {
    int n = blockIdx.x * 256 + threadIdx.x;
    if (n >= GSZ) return;
    float4 g = g_grid[n];
    if (g.w <= 0.0f) return;
    const float inv = 1.0f / fmaxf(g.w, 1e-10f);
    float vx = g.x * inv;
    float vy = g.y * inv + DTf * (-9.8f);
    float vz = g.z * inv;
    const int i = n >> 12;
    const int j = (n >> 6) & 63;
    const int k = n & 63;
    if ((i < 3 && vx < 0.f) || (i >= NG - 3 && vx > 0.f)) vx = 0.f;
    if ((j < 3 && vy < 0.f) || (j >= NG - 3 && vy > 0.f)) vy = 0.f;
    if ((k < 3 && vz < 0.f) || (k >= NG - 3 && vz > 0.f)) vz = 0.f;
    g_grid[n] = make_float4(vx, vy, vz, 0.f);
}

// ---------------------------------------------------------------------------
// Sorted G2P: gather 27 grid nodes (warp-local addresses), write (v',C')
// coalesced to g_outbuf:
//  o0=(v0,v1,v2,C00) o1=(C01,C02,C10,C11) o2=(C12,C20,C21,C22)
__global__ void __launch_bounds__(256) g2p_kernel() {
    int i = blockIdx.x * 256 + threadIdx.x;
    if (i >= NP) return;
    const float4 q0 = __ldg(&g_pk[4 * i]);
    const float px = q0.x, py = q0.y, pz = q0.z;

    const float gx = px * INV_DXf, gy = py * INV_DXf, gz = pz * INV_DXf;
    const int bx = clampi((int)floorf(gx - 0.5f), 0, NG - 3);
    const int by = clampi((int)floorf(gy - 0.5f), 0, NG - 3);
    const int bz = clampi((int)floorf(gz - 0.5f), 0, NG - 3);
    const float fx = gx - (float)bx, fy = gy - (float)by, fz = gz - (float)bz;

    float wx[3], wy[3], wz[3];
    wx[0] = 0.5f * (1.5f - fx) * (1.5f - fx);
    wx[1] = 0.75f - (fx - 1.0f) * (fx - 1.0f);
    wx[2] = 0.5f * (fx - 0.5f) * (fx - 0.5f);
    wy[0] = 0.5f * (1.5f - fy) * (1.5f - fy);
    wy[1] = 0.75f - (fy - 1.0f) * (fy - 1.0f);
    wy[2] = 0.5f * (fy - 0.5f) * (fy - 0.5f);
    wz[0] = 0.5f * (1.5f - fz) * (1.5f - fz);
    wz[1] = 0.75f - (fz - 1.0f) * (fz - 1.0f);
    wz[2] = 0.5f * (fz - 0.5f) * (fz - 0.5f);

    float vn0 = 0.f, vn1 = 0.f, vn2 = 0.f;
    float B[3][3] = {{0.f,0.f,0.f},{0.f,0.f,0.f},{0.f,0.f,0.f}};

#pragma unroll
    for (int a = 0; a < 3; a++) {
        const float dpi = (float)a - fx;
#pragma unroll
        for (int b = 0; b < 3; b++) {
            const float dpj = (float)b - fy;
            const float wab = wx[a] * wy[b];
            const int rowbase = ((bx + a) * NG + (by + b)) * NG + bz;
#pragma unroll
            for (int k = 0; k < 3; k++) {
                const float dpk = (float)k - fz;
                const float w = wab * wz[k];
                const float4 g = __ldg(&g_grid[rowbase + k]);
                vn0 += w * g.x; vn1 += w * g.y; vn2 += w * g.z;
                B[0][0] += w * g.x * dpi; B[0][1] += w * g.x * dpj; B[0][2] += w * g.x * dpk;
                B[1][0] += w * g.y * dpi; B[1][1] += w * g.y * dpj; B[1][2] += w * g.y * dpk;
                B[2][0] += w * g.z * dpi; B[2][1] += w * g.z * dpj; B[2][2] += w * g.z * dpk;
            }
        }
    }

    float4* dst = &g_outbuf[3 * i];
    dst[0] = make_float4(vn0, vn1, vn2, C_COEF * B[0][0]);
    dst[1] = make_float4(C_COEF * B[0][1], C_COEF * B[0][2],
                         C_COEF * B[1][0], C_COEF * B[1][1]);
    dst[2] = make_float4(C_COEF * B[1][2], C_COEF * B[2][0],
                         C_COEF * B[2][1], C_COEF * B[2][2]);
}

// ---------------------------------------------------------------------------
// Final: original order. Gather (v',C') via slot; F and x staged in via
// coalesced float4; ALL outputs staged through smem and written as float4.
// Also zeroes g_grid for the next run.
__global__ void __launch_bounds__(256) final_kernel(
    const float* __restrict__ x, const float* __restrict__ F,
    float* __restrict__ out)
{
    __shared__ float sxi[768];    // x in
    __shared__ float sFi[2304];   // F in
    __shared__ float ox_[768];    // x' out
    __shared__ float ov_[768];    // v' out
    __shared__ float oC_[2304];   // C' out
    __shared__ float oF_[2304];   // F' out

    const int tid   = threadIdx.x;
    const int pbase = blockIdx.x * 256;
    const int gid   = pbase + tid;
    if (gid < GSZ) g_grid[gid] = make_float4(0.f, 0.f, 0.f, 0.f);

    const bool full = (pbase + 256 <= NP);
    if (full) {
        const float4* x4 = reinterpret_cast<const float4*>(x + 3 * pbase);
        const float4* F4 = reinterpret_cast<const float4*>(F + 9 * pbase);
        if (tid < 192) reinterpret_cast<float4*>(sxi)[tid] = __ldcs(&x4[tid]);
#pragma unroll
        for (int i = tid; i < 576; i += 256)
            reinterpret_cast<float4*>(sFi)[i] = __ldcs(&F4[i]);
    } else {
        const int nfl3 = (NP > pbase) ? (NP - pbase) * 3 : 0;
        const int nfl9 = (NP > pbase) ? (NP - pbase) * 9 : 0;
        for (int i = tid; i < nfl3; i += 256) sxi[i] = x[3 * pbase + i];
        for (int i = tid; i < nfl9; i += 256) sFi[i] = F[9 * pbase + i];
    }
    __syncthreads();

    const int p = gid;
    if (p < NP) {
        const int s = g_slot[p];
        const float4* src = &g_outbuf[3 * s];
        const float4 o0 = __ldg(&src[0]);
        const float4 o1 = __ldg(&src[1]);
        const float4 o2 = __ldg(&src[2]);

        const float vn0 = o0.x, vn1 = o0.y, vn2 = o0.z;
        ox_[3 * tid + 0] = sxi[3 * tid + 0] + DTf * vn0;
        ox_[3 * tid + 1] = sxi[3 * tid + 1] + DTf * vn1;
        ox_[3 * tid + 2] = sxi[3 * tid + 2] + DTf * vn2;
        ov_[3 * tid + 0] = vn0;
        ov_[3 * tid + 1] = vn1;
        ov_[3 * tid + 2] = vn2;

        const float Cn[3][3] = {{o0.w, o1.x, o1.y},
                                {o1.z, o1.w, o2.x},
                                {o2.y, o2.z, o2.w}};
#pragma unroll
        for (int r = 0; r < 3; r++)
#pragma unroll
            for (int cjj = 0; cjj < 3; cjj++)
                oC_[9 * tid + 3 * r + cjj] = Cn[r][cjj];

#pragma unroll
        for (int r = 0; r < 3; r++) {
            const float m0 = (r == 0 ? 1.f : 0.f) + DTf * Cn[r][0];
            const float m1 = (r == 1 ? 1.f : 0.f) + DTf * Cn[r][1];
            const float m2 = (r == 2 ? 1.f : 0.f) + DTf * Cn[r][2];
#pragma unroll
            for (int cjj = 0; cjj < 3; cjj++)
                oF_[9 * tid + 3 * r + cjj] =
                    m0 * sFi[9 * tid + 0 + cjj] +
                    m1 * sFi[9 * tid + 3 + cjj] +
                    m2 * sFi[9 * tid + 6 + cjj];
        }
    }
    __syncthreads();

    if (full) {
        float4* dx = reinterpret_cast<float4*>(out + (size_t)3 * pbase);
        float4* dv = reinterpret_cast<float4*>(out + (size_t)3 * NP + 3 * pbase);
        float4* dC = reinterpret_cast<float4*>(out + (size_t)6 * NP + 9 * pbase);
        float4* dF = reinterpret_cast<float4*>(out + (size_t)15 * NP + 9 * pbase);
        if (tid < 192) {
            __stcs(&dx[tid], reinterpret_cast<float4*>(ox_)[tid]);
            __stcs(&dv[tid], reinterpret_cast<float4*>(ov_)[tid]);
        }
#pragma unroll
        for (int i = tid; i < 576; i += 256) {
            __stcs(&dC[i], reinterpret_cast<float4*>(oC_)[i]);
            __stcs(&dF[i], reinterpret_cast<float4*>(oF_)[i]);
        }
    } else if (pbase < NP) {
        const int nfl3 = (NP - pbase) * 3;
        const int nfl9 = (NP - pbase) * 9;
        for (int i = tid; i < nfl3; i += 256) {
            out[3 * pbase + i] = ox_[i];
            out[(size_t)3 * NP + 3 * pbase + i] = ov_[i];
        }
        for (int i = tid; i < nfl9; i += 256) {
            out[(size_t)6 * NP + 9 * pbase + i] = oC_[i];
            out[(size_t)15 * NP + 9 * pbase + i] = oF_[i];
        }
    }
}

// ---------------------------------------------------------------------------
extern "C" void kernel_launch(void* const* d_in, const int* in_sizes, int n_in,
                              void* d_out, int out_size)
{
    const float* x      = (const float*)d_in[0];
    const float* v      = (const float*)d_in[1];
    const float* C      = (const float*)d_in[2];
    const float* F      = (const float*)d_in[3];
    const float* stress = (const float*)d_in[4];
    float* out = (float*)d_out;

    const int gblocks = (GSZ + 255) / 256;
    const int pblocks = (NP + 255) / 256;

    hist_kernel<<<pblocks, 256>>>(x);
    scan1_kernel<<<SCAN_BLOCKS, SCAN_T>>>();
    scan23_kernel<<<SCAN_BLOCKS, SCAN_T>>>();
    scatter_kernel<<<pblocks, 256>>>(x, v, C, stress);
    p2g_cell_kernel<<<(GSZ + 127) / 128, 128>>>();
    grid_kernel<<<gblocks, 256>>>();
    g2p_kernel<<<pblocks, 256>>>();
    final_kernel<<<pblocks, 256>>>(x, F, out);
}